// round 1
// baseline (speedup 1.0000x reference)
#include <cuda_runtime.h>
#include <math.h>

#define MM 4
#define N_ITEM 40000
#define N_USER 10000
#define NN 50000
#define DD 128
#define DX 64
#define EE 400000
#define BB 4096

// ---------------- scratch (device globals; allocation-free) ----------------
__device__ float g_x   [MM*NN*DD];   // normalized node features per modality
__device__ float g_xt  [MM*NN*DD];   // x @ convW
__device__ float g_agg [MM*NN*DD];   // aggregate, then h in-place
__device__ float g_xh  [MM*NN*DX];   // lrelu(x@lin1W^T+b) + id_emb
__device__ float g_reps[MM*NN*DX];   // per-modality output reps
__device__ float g_ip  [EE];
__device__ float g_w   [EE];
__device__ float g_ev  [EE];
__device__ float g_deg [NN];
__device__ float g_dinv[NN];
__device__ unsigned g_wmax[NN];
__device__ float g_esum[NN];
__device__ float g_kmod[MM*DX];
__device__ float g_kp  [MM*DX];
__device__ float g_vp  [MM*DX];

__device__ __forceinline__ float lrelu(float x){ return x > 0.f ? x : 0.01f*x; }
__device__ __forceinline__ float wsum(float v){
  #pragma unroll
  for (int o = 16; o; o >>= 1) v += __shfl_xor_sync(0xffffffffu, v, o);
  return v;
}

// ---------------- generic batched SGEMM with fused epilogues ----------------
// C[M,N] = epi(A[M,K] @ B)  ; BT=false: B[K,N], BT=true: B[N,K] (i.e. @ B^T)
// EPI 0: none | 1: tanh(acc+bias) | 2: lrelu(acc+bias)+add | 3: lrelu(acc+bias+add)
template<bool BT, int EPI>
__global__ void __launch_bounds__(256) k_gemm(
    const float* __restrict__ A, const float* __restrict__ B, float* __restrict__ C,
    int M, int N, int K, long sA, long sB, long sC,
    const float* __restrict__ bias, long sBias,
    const float* __restrict__ add, long sAdd)
{
  __shared__ float As[16][68];
  __shared__ float Bs[16][68];
  int z = blockIdx.z;
  A += (long)z * sA;  B += (long)z * sB;  C += (long)z * sC;
  if (EPI)      bias += (long)z * sBias;
  if (EPI >= 2) add  += (long)z * sAdd;
  int m0 = blockIdx.y * 64, n0 = blockIdx.x * 64;
  int tid = threadIdx.x;
  int ar = tid >> 2, ak = (tid & 3) << 2;   // 64 rows x 16 k
  int ty = tid >> 4, tx = tid & 15;
  float acc[4][4] = {};

  for (int k0 = 0; k0 < K; k0 += 16) {
    float4 av = make_float4(0,0,0,0);
    int arow = m0 + ar;
    if (arow < M) av = *(const float4*)(A + (long)arow*K + k0 + ak);
    As[ak+0][ar]=av.x; As[ak+1][ar]=av.y; As[ak+2][ar]=av.z; As[ak+3][ar]=av.w;
    if (BT) {
      float4 bv = make_float4(0,0,0,0);
      int brow = n0 + ar;
      if (brow < N) bv = *(const float4*)(B + (long)brow*K + k0 + ak);
      Bs[ak+0][ar]=bv.x; Bs[ak+1][ar]=bv.y; Bs[ak+2][ar]=bv.z; Bs[ak+3][ar]=bv.w;
    } else {
      int bk = tid >> 4, bn = (tid & 15) << 2;
      float4 bv = make_float4(0,0,0,0);
      int bcol = n0 + bn;
      if (bcol < N) bv = *(const float4*)(B + (long)(k0+bk)*N + bcol);
      Bs[bk][bn+0]=bv.x; Bs[bk][bn+1]=bv.y; Bs[bk][bn+2]=bv.z; Bs[bk][bn+3]=bv.w;
    }
    __syncthreads();
    #pragma unroll
    for (int k = 0; k < 16; k++) {
      float4 a4 = *(const float4*)&As[k][ty << 2];
      float4 b4 = *(const float4*)&Bs[k][tx << 2];
      float a[4] = {a4.x, a4.y, a4.z, a4.w};
      float b[4] = {b4.x, b4.y, b4.z, b4.w};
      #pragma unroll
      for (int i = 0; i < 4; i++)
        #pragma unroll
        for (int j = 0; j < 4; j++)
          acc[i][j] += a[i] * b[j];
    }
    __syncthreads();
  }
  #pragma unroll
  for (int i = 0; i < 4; i++) {
    int row = m0 + (ty << 2) + i;
    if (row >= M) break;
    #pragma unroll
    for (int j = 0; j < 4; j++) {
      int col = n0 + (tx << 2) + j;   // N is a multiple of 64 -> always in range
      float v = acc[i][j];
      if (EPI == 1)      v = tanhf(v + bias[col]);
      else if (EPI == 2) v = lrelu(v + bias[col]) + add[(long)row*N + col];
      else if (EPI == 3) v = lrelu(v + bias[col] + add[(long)row*N + col]);
      C[(long)row*N + col] = v;
    }
  }
}

// ---------------- degree ----------------
__global__ void k_zero_deg(){
  int i = blockIdx.x*256 + threadIdx.x;
  if (i < NN) g_deg[i] = 0.f;
}
__global__ void k_deg(const int* __restrict__ src){
  int e = blockIdx.x*256 + threadIdx.x;
  if (e < EE) atomicAdd(&g_deg[src[e]], 1.f);
}
__global__ void k_dinv(){
  int i = blockIdx.x*256 + threadIdx.x;
  if (i < NN) { float d = g_deg[i]; g_dinv[i] = d > 0.f ? 1.f/sqrtf(d) : 0.f; }
}

// ---------------- node-feature build: normalize rows of 128 ----------------
__global__ void k_norm_items(const float* __restrict__ feats){
  int g = blockIdx.x*256 + threadIdx.x;
  int w = g >> 5, lane = g & 31;
  if (w >= MM*N_ITEM) return;
  int m = w / N_ITEM, i = w - m*N_ITEM;
  const float* in = feats + ((long)m*N_ITEM + i)*DD;
  float v[4], ss = 0.f;
  #pragma unroll
  for (int q = 0; q < 4; q++){ v[q] = in[q*32 + lane]; ss += v[q]*v[q]; }
  ss = wsum(ss);
  float rn = 1.f / fmaxf(sqrtf(ss), 1e-12f);
  float* o = g_x + ((long)m*NN + i)*DD;
  #pragma unroll
  for (int q = 0; q < 4; q++) o[q*32 + lane] = v[q]*rn;
}
__global__ void k_norm_users(){
  int g = blockIdx.x*256 + threadIdx.x;
  int w = g >> 5, lane = g & 31;
  if (w >= MM*N_USER) return;
  int m = w / N_USER, i = w - m*N_USER;
  float* p = g_x + ((long)m*NN + N_ITEM + i)*DD;
  float v[4], ss = 0.f;
  #pragma unroll
  for (int q = 0; q < 4; q++){ v[q] = p[q*32 + lane]; ss += v[q]*v[q]; }
  ss = wsum(ss);
  float rn = 1.f / fmaxf(sqrtf(ss), 1e-12f);
  #pragma unroll
  for (int q = 0; q < 4; q++) p[q*32 + lane] = v[q]*rn;
}
__global__ void k_hnorm(){
  int g = blockIdx.x*256 + threadIdx.x;
  int w = g >> 5, lane = g & 31;
  if (w >= MM*NN) return;
  float* p = g_agg + (long)w*DD;
  float v[4], ss = 0.f;
  #pragma unroll
  for (int q = 0; q < 4; q++){ v[q] = p[q*32 + lane]; ss += v[q]*v[q]; }
  ss = wsum(ss);
  float rn = 1.f / fmaxf(sqrtf(ss), 1e-12f);
  #pragma unroll
  for (int q = 0; q < 4; q++) p[q*32 + lane] = lrelu(v[q]*rn);
}

// ---------------- edge pipeline (per modality) ----------------
__global__ void k_edge_init(float* __restrict__ aggm, const float* __restrict__ cb){
  int idx = blockIdx.x*256 + threadIdx.x;
  if (idx >= NN*DD) return;
  int c = idx & 127;
  aggm[idx] = cb[c];
  if (c == 0) { int i = idx >> 7; g_wmax[i] = 0x007FFFFFu; g_esum[i] = 0.f; }
}
__global__ void k_ip(const float* __restrict__ xt,
                     const int* __restrict__ src, const int* __restrict__ dst){
  int g = blockIdx.x*256 + threadIdx.x;
  int w = g >> 5;
  if (w >= EE) return;
  int lane = g & 31;
  const float* ps = xt + (long)src[w]*DD;
  const float* pd = xt + (long)dst[w]*DD;
  float acc = 0.f;
  #pragma unroll
  for (int q = 0; q < 4; q++){
    float xs = ps[q*32 + lane], xd = pd[q*32 + lane];
    acc += xd * (xs > 0.f ? xs : 0.01f*xs);
  }
  acc = wsum(acc);
  if (lane == 0) g_ip[w] = acc;
}
__global__ void k_wm(const int* __restrict__ src, const int* __restrict__ dst){
  int e = blockIdx.x*256 + threadIdx.x;
  if (e >= EE) return;
  float ip = g_ip[e];
  float di = g_dinv[src[e]];
  float wv = ip / (1.f + expf(-di*ip));        // ip * sigmoid(dinv*ip)
  g_w[e] = wv;
  unsigned u = __float_as_uint(wv);
  u = (u & 0x80000000u) ? ~u : (u | 0x80000000u);   // order-preserving encode
  atomicMax(&g_wmax[dst[e]], u);
}
__global__ void k_exp(const int* __restrict__ dst){
  int e = blockIdx.x*256 + threadIdx.x;
  if (e >= EE) return;
  int d = dst[e];
  unsigned u = g_wmax[d];
  float wm = __uint_as_float((u & 0x80000000u) ? (u ^ 0x80000000u) : ~u);
  float ev = expf(g_w[e] - wm);
  g_ev[e] = ev;
  atomicAdd(&g_esum[d], ev);
}
__global__ void k_agg(const float* __restrict__ xt,
                      const int* __restrict__ src, const int* __restrict__ dst,
                      float* __restrict__ aggm){
  int g = blockIdx.x*256 + threadIdx.x;
  int w = g >> 5;
  if (w >= EE) return;
  int lane = g & 31;
  int d = dst[w];
  float att = g_ev[w] / (g_esum[d] + 1e-16f);
  const float* ps = xt + (long)src[w]*DD;
  float* pa = aggm + (long)d*DD;
  #pragma unroll
  for (int q = 0; q < 4; q++)
    atomicAdd(&pa[q*32 + lane], att * ps[q*32 + lane]);
}

// ---------------- tail ----------------
__global__ void k_mean(float* __restrict__ out_rep){
  int i = blockIdx.x*256 + threadIdx.x;
  if (i < MM*DX) g_kmod[i] = 0.f;                  // zero accumulator for k_kmod
  if (i < NN*DX)
    out_rep[i] = 0.25f * (g_reps[i] + g_reps[(long)NN*DX + i]
                        + g_reps[2L*NN*DX + i] + g_reps[3L*NN*DX + i]);
}
__global__ void __launch_bounds__(64) k_kmod(const int* __restrict__ pi){
  int m = blockIdx.y, j = threadIdx.x;
  int b0 = blockIdx.x * 64;
  float acc = 0.f;
  #pragma unroll 4
  for (int t = 0; t < 64; t++){
    int p = pi[b0 + t];
    acc += g_reps[((long)m*NN + p)*DX + j];
  }
  atomicAdd(&g_kmod[m*DX + j], acc);
}
__global__ void k_kpvp(const float* __restrict__ kW, const float* __restrict__ vW){
  int tid = threadIdx.x;
  int m = tid >> 6, j = tid & 63;
  float s1 = 0.f, s2 = 0.f;
  #pragma unroll 8
  for (int k = 0; k < DX; k++){
    float km = g_kmod[m*DX + k] * (1.f/BB);
    s1 += km * kW[j*DX + k];
    s2 += km * vW[j*DX + k];
  }
  g_kp[m*DX + j] = s1;
  g_vp[m*DX + j] = s2;
}
__global__ void __launch_bounds__(64) k_final(
    const float* __restrict__ rep,
    const int* __restrict__ un, const int* __restrict__ pi, const int* __restrict__ ni,
    const float* __restrict__ qW,
    const float* __restrict__ mpW1, const float* __restrict__ mpb1,
    const float* __restrict__ mpW2, const float* __restrict__ mpb2,
    float* __restrict__ out_pos, float* __restrict__ out_neg, float* __restrict__ out_pred)
{
  int b = blockIdx.x, j = threadIdx.x;
  __shared__ float su[DX], sq[DX], sa[DX], sp[DX], sn[DX], sc[MM], red[DX];
  su[j] = rep[(long)un[b]*DX + j];
  sp[j] = rep[(long)pi[b]*DX + j];
  sn[j] = rep[(long)ni[b]*DX + j];
  __syncthreads();
  float q = 0.f;
  #pragma unroll 8
  for (int k = 0; k < DX; k++) q += su[k] * qW[j*DX + k];
  sq[j] = q;
  __syncthreads();
  if (j < MM){
    float s = 0.f;
    #pragma unroll 8
    for (int k = 0; k < DX; k++) s += sq[k] * g_kp[j*DX + k];
    sc[j] = s * 0.125f;                       // / sqrt(64)
  }
  __syncthreads();
  float mx = fmaxf(fmaxf(sc[0], sc[1]), fmaxf(sc[2], sc[3]));
  float e0 = expf(sc[0]-mx), e1 = expf(sc[1]-mx), e2 = expf(sc[2]-mx), e3 = expf(sc[3]-mx);
  float es = e0 + e1 + e2 + e3;
  float av = (e0*g_vp[0*DX+j] + e1*g_vp[1*DX+j] + e2*g_vp[2*DX+j] + e3*g_vp[3*DX+j]) / es;
  sa[j] = av;
  red[j] = av * sp[j];
  __syncthreads();
  for (int s = 32; s > 0; s >>= 1){ if (j < s) red[j] += red[j+s]; __syncthreads(); }
  if (j == 0) out_pos[b] = red[0];
  __syncthreads();
  red[j] = av * sn[j];
  __syncthreads();
  for (int s = 32; s > 0; s >>= 1){ if (j < s) red[j] += red[j+s]; __syncthreads(); }
  if (j == 0) out_neg[b] = red[0];
  __syncthreads();
  float h = mpb1[j];
  #pragma unroll 8
  for (int k = 0; k < DX; k++) h += sa[k] * mpW1[j*2*DX + k];
  #pragma unroll 8
  for (int k = 0; k < DX; k++) h += sp[k] * mpW1[j*2*DX + DX + k];
  h = lrelu(h);
  red[j] = h * mpW2[j];
  __syncthreads();
  for (int s = 32; s > 0; s >>= 1){ if (j < s) red[j] += red[j+s]; __syncthreads(); }
  if (j == 0) out_pred[b] = red[0] + mpb2[0];
}

// ---------------- host ----------------
extern "C" void kernel_launch(void* const* d_in, const int* in_sizes, int n_in,
                              void* d_out, int out_size)
{
  const float* feats  = (const float*)d_in[0];
  const float* uf     = (const float*)d_in[1];
  const float* userW  = (const float*)d_in[2];
  const float* userb  = (const float*)d_in[3];
  const float* convW  = (const float*)d_in[4];
  const float* convb  = (const float*)d_in[5];
  const float* lin1W  = (const float*)d_in[6];
  const float* lin1b  = (const float*)d_in[7];
  const float* g1W    = (const float*)d_in[8];
  const float* g1b    = (const float*)d_in[9];
  const float* id_emb = (const float*)d_in[10];
  const float* qW     = (const float*)d_in[11];
  const float* kW     = (const float*)d_in[12];
  const float* vW     = (const float*)d_in[13];
  const float* mpW1   = (const float*)d_in[14];
  const float* mpb1   = (const float*)d_in[15];
  const float* mpW2   = (const float*)d_in[16];
  const float* mpb2   = (const float*)d_in[17];
  const int*   eidx   = (const int*)d_in[18];
  const int*   un     = (const int*)d_in[19];
  const int*   pi     = (const int*)d_in[20];
  const int*   ni     = (const int*)d_in[21];
  const int *src = eidx, *dst = eidx + EE;

  float* out      = (float*)d_out;
  float* out_pos  = out;
  float* out_neg  = out + BB;
  float* out_rep  = out + 2*BB;
  float* out_pred = out + 2*BB + (long)NN*DX;

  void* p;
  cudaGetSymbolAddress(&p, g_x);    float* x    = (float*)p;
  cudaGetSymbolAddress(&p, g_xt);   float* xt   = (float*)p;
  cudaGetSymbolAddress(&p, g_agg);  float* agg  = (float*)p;
  cudaGetSymbolAddress(&p, g_xh);   float* xh   = (float*)p;
  cudaGetSymbolAddress(&p, g_reps); float* reps = (float*)p;

  // degrees (src-degree is modality-invariant)
  k_zero_deg<<<(NN+255)/256, 256>>>();
  k_deg<<<(EE+255)/256, 256>>>(src);
  k_dinv<<<(NN+255)/256, 256>>>();

  // build x: normalized items + tanh user transform normalized
  k_norm_items<<<(MM*N_ITEM*32 + 255)/256, 256>>>(feats);
  {
    dim3 g(DD/64, (N_USER+63)/64, MM);
    k_gemm<true,1><<<g, 256>>>(uf, userW, x + (long)N_ITEM*DD, N_USER, DD, DD,
                               0, (long)DD*DD, (long)NN*DD, userb, DD, nullptr, 0);
  }
  k_norm_users<<<(MM*N_USER*32 + 255)/256, 256>>>();

  // xt = x @ convW
  {
    dim3 g(DD/64, (NN+63)/64, MM);
    k_gemm<false,0><<<g, 256>>>(x, convW, xt, NN, DD, DD,
                                (long)NN*DD, (long)DD*DD, (long)NN*DD,
                                nullptr, 0, nullptr, 0);
  }
  // xh = lrelu(x @ lin1W^T + b) + id_emb
  {
    dim3 g(DX/64, (NN+63)/64, MM);
    k_gemm<true,2><<<g, 256>>>(x, lin1W, xh, NN, DX, DD,
                               (long)NN*DD, (long)DX*DD, (long)NN*DX,
                               lin1b, DX, id_emb, 0);
  }

  // edge pipeline per modality (keeps 25.6MB xt hot in L2)
  for (int m = 0; m < MM; m++){
    const float* xtm = xt + (long)m*NN*DD;
    float* aggm = agg + (long)m*NN*DD;
    k_edge_init<<<(NN*DD + 255)/256, 256>>>(aggm, convb + m*DD);
    k_ip <<<(EE*32 + 255)/256, 256>>>(xtm, src, dst);
    k_wm <<<(EE + 255)/256, 256>>>(src, dst);
    k_exp<<<(EE + 255)/256, 256>>>(dst);
    k_agg<<<(EE*32 + 255)/256, 256>>>(xtm, src, dst, aggm);
  }
  k_hnorm<<<(MM*NN*32 + 255)/256, 256>>>();

  // reps = lrelu(h @ g1W^T + g1b + xh)
  {
    dim3 g(DX/64, (NN+63)/64, MM);
    k_gemm<true,3><<<g, 256>>>(agg, g1W, reps, NN, DX, DD,
                               (long)NN*DD, (long)DX*DD, (long)NN*DX,
                               g1b, DX, xh, (long)NN*DX);
  }

  k_mean<<<(NN*DX + 255)/256, 256>>>(out_rep);
  k_kmod<<<dim3(BB/64, MM), 64>>>(pi);
  k_kpvp<<<1, 256>>>(kW, vW);
  k_final<<<BB, 64>>>(out_rep, un, pi, ni, qW, mpW1, mpb1, mpW2, mpb2,
                      out_pos, out_neg, out_pred);
}

// round 2
// speedup vs baseline: 1.0774x; 1.0774x over previous
#include <cuda_runtime.h>
#include <math.h>

#define MM 4
#define N_ITEM 40000
#define N_USER 10000
#define NN 50000
#define DD 128
#define DX 64
#define EE 400000
#define BB 4096

// ---------------- scratch (device globals; allocation-free) ----------------
__device__ float g_x   [MM*NN*DD];
__device__ float g_xt  [MM*NN*DD];
__device__ float g_agg [MM*NN*DD];
__device__ float g_xh  [MM*NN*DX];
__device__ float g_reps[MM*NN*DX];
__device__ float g_w   [EE];
__device__ float g_ev  [EE];
__device__ float g_deg [NN];
__device__ float g_dinv[NN];
__device__ unsigned g_wmax[NN];
__device__ float g_esum[NN];
__device__ float g_kmod[MM*DX];
__device__ float g_kp  [MM*DX];
__device__ float g_vp  [MM*DX];

__device__ __forceinline__ float lrelu(float x){ return x > 0.f ? x : 0.01f*x; }
__device__ __forceinline__ float wsum(float v){
  #pragma unroll
  for (int o = 16; o; o >>= 1) v += __shfl_xor_sync(0xffffffffu, v, o);
  return v;
}

// ---------------- batched SGEMM: 128xBN tile, 8x(BN/16) per-thread ----------
// C[M,N] = epi(A[M,K] @ B) ; BT=false: B[K,N], BT=true: B[N,K]
// EPI 0: none | 1: tanh(+bias) | 2: lrelu(+bias)+add | 3: lrelu(+bias+add)
template<int BN, bool BT, int EPI>
__global__ void __launch_bounds__(256) k_gemm(
    const float* __restrict__ A, const float* __restrict__ B, float* __restrict__ C,
    int M, int N, int K, long sA, long sB, long sC,
    const float* __restrict__ bias, long sBias,
    const float* __restrict__ add, long sAdd)
{
  constexpr int BM = 128, BK = 16, TM = 8, TN = BN/16;
  __shared__ float As[BK][BM+4];
  __shared__ float Bs[BK][BN+4];
  int z = blockIdx.z;
  A += (long)z * sA;  B += (long)z * sB;  C += (long)z * sC;
  if (EPI)      bias += (long)z * sBias;
  if (EPI >= 2) add  += (long)z * sAdd;
  int m0 = blockIdx.y * BM, n0 = blockIdx.x * BN;
  int tid = threadIdx.x;
  int tx = tid & 15, ty = tid >> 4;
  float acc[TM][TN] = {};

  for (int k0 = 0; k0 < K; k0 += BK) {
    // A tile: BM x BK = 512 float4 -> 2 per thread (transpose into As[k][m])
    #pragma unroll
    for (int f = 0; f < 2; f++) {
      int idx = tid + f*256;
      int row = idx >> 2, kq = (idx & 3) << 2;
      float4 v = make_float4(0,0,0,0);
      if (m0 + row < M) v = *(const float4*)(A + (long)(m0+row)*K + k0 + kq);
      As[kq+0][row]=v.x; As[kq+1][row]=v.y; As[kq+2][row]=v.z; As[kq+3][row]=v.w;
    }
    if (BT) {
      constexpr int F = (BN*BK/4)/256;   // 2 for BN=128, 1 for BN=64
      #pragma unroll
      for (int f = 0; f < F; f++) {
        int idx = tid + f*256;
        int row = idx >> 2, kq = (idx & 3) << 2;
        float4 v = *(const float4*)(B + (long)(n0+row)*K + k0 + kq);
        Bs[kq+0][row]=v.x; Bs[kq+1][row]=v.y; Bs[kq+2][row]=v.z; Bs[kq+3][row]=v.w;
      }
    } else {
      constexpr int F = (BK*BN/4)/256;
      #pragma unroll
      for (int f = 0; f < F; f++) {
        int idx = tid + f*256;
        int kk = idx / (BN/4), nq = (idx % (BN/4)) << 2;
        float4 v = *(const float4*)(B + (long)(k0+kk)*N + n0 + nq);
        *(float4*)&Bs[kk][nq] = v;
      }
    }
    __syncthreads();
    #pragma unroll
    for (int k = 0; k < BK; k++) {
      float a[TM], b[TN];
      *(float4*)&a[0] = *(const float4*)&As[k][ty<<2];
      *(float4*)&a[4] = *(const float4*)&As[k][64 + (ty<<2)];
      *(float4*)&b[0] = *(const float4*)&Bs[k][tx<<2];
      if constexpr (TN == 8)
        *(float4*)&b[4] = *(const float4*)&Bs[k][64 + (tx<<2)];
      #pragma unroll
      for (int i = 0; i < TM; i++)
        #pragma unroll
        for (int j = 0; j < TN; j++)
          acc[i][j] += a[i] * b[j];
    }
    __syncthreads();
  }
  #pragma unroll
  for (int i = 0; i < TM; i++) {
    int row = m0 + ((i < 4) ? (ty<<2)+i : 64 + (ty<<2) + (i-4));
    if (row >= M) continue;
    #pragma unroll
    for (int j = 0; j < TN; j++) {
      int col;
      if constexpr (TN == 8) col = n0 + ((j < 4) ? (tx<<2)+j : 64 + (tx<<2) + (j-4));
      else                   col = n0 + (tx<<2) + j;
      float v = acc[i][j];
      if (EPI == 1)      v = tanhf(v + bias[col]);
      else if (EPI == 2) v = lrelu(v + bias[col]) + add[(long)row*N + col];
      else if (EPI == 3) v = lrelu(v + bias[col] + add[(long)row*N + col]);
      C[(long)row*N + col] = v;
    }
  }
}

// ---------------- degree ----------------
__global__ void k_zero_deg(){
  int i = blockIdx.x*256 + threadIdx.x;
  if (i < NN) g_deg[i] = 0.f;
}
__global__ void k_deg(const int* __restrict__ src){
  int e = blockIdx.x*256 + threadIdx.x;
  if (e < EE) atomicAdd(&g_deg[src[e]], 1.f);
}
__global__ void k_dinv(){
  int i = blockIdx.x*256 + threadIdx.x;
  if (i < NN) { float d = g_deg[i]; g_dinv[i] = d > 0.f ? 1.f/sqrtf(d) : 0.f; }
}

// ---------------- node-feature normalize ----------------
__global__ void k_norm_items(const float* __restrict__ feats){
  int g = blockIdx.x*256 + threadIdx.x;
  int w = g >> 5, lane = g & 31;
  if (w >= MM*N_ITEM) return;
  int m = w / N_ITEM, i = w - m*N_ITEM;
  const float* in = feats + ((long)m*N_ITEM + i)*DD;
  float v[4], ss = 0.f;
  #pragma unroll
  for (int q = 0; q < 4; q++){ v[q] = in[q*32 + lane]; ss += v[q]*v[q]; }
  ss = wsum(ss);
  float rn = 1.f / fmaxf(sqrtf(ss), 1e-12f);
  float* o = g_x + ((long)m*NN + i)*DD;
  #pragma unroll
  for (int q = 0; q < 4; q++) o[q*32 + lane] = v[q]*rn;
}
__global__ void k_norm_users(){
  int g = blockIdx.x*256 + threadIdx.x;
  int w = g >> 5, lane = g & 31;
  if (w >= MM*N_USER) return;
  int m = w / N_USER, i = w - m*N_USER;
  float* p = g_x + ((long)m*NN + N_ITEM + i)*DD;
  float v[4], ss = 0.f;
  #pragma unroll
  for (int q = 0; q < 4; q++){ v[q] = p[q*32 + lane]; ss += v[q]*v[q]; }
  ss = wsum(ss);
  float rn = 1.f / fmaxf(sqrtf(ss), 1e-12f);
  #pragma unroll
  for (int q = 0; q < 4; q++) p[q*32 + lane] = v[q]*rn;
}
// h = lrelu(l2norm(agg + convb[m]))
__global__ void k_hnorm(const float* __restrict__ convb){
  int g = blockIdx.x*256 + threadIdx.x;
  int w = g >> 5, lane = g & 31;
  if (w >= MM*NN) return;
  int m = w / NN;
  float* p = g_agg + (long)w*DD;
  const float* cb = convb + m*DD;
  float v[4], ss = 0.f;
  #pragma unroll
  for (int q = 0; q < 4; q++){ v[q] = p[q*32 + lane] + cb[q*32 + lane]; ss += v[q]*v[q]; }
  ss = wsum(ss);
  float rn = 1.f / fmaxf(sqrtf(ss), 1e-12f);
  #pragma unroll
  for (int q = 0; q < 4; q++) p[q*32 + lane] = lrelu(v[q]*rn);
}

// ---------------- edge pipeline ----------------
__global__ void k_zero_agg(){
  int i = blockIdx.x*256 + threadIdx.x;
  if (i < MM*NN*DD/4) ((float4*)g_agg)[i] = make_float4(0,0,0,0);
}
__global__ void k_einit(){
  int i = blockIdx.x*256 + threadIdx.x;
  if (i < NN){ g_wmax[i] = 0x007FFFFFu; g_esum[i] = 0.f; }
}
// fused: ip dot + gate + segment-max (warp per edge, float4 lanes)
__global__ void k_ipwm(const float* __restrict__ xt,
                       const int* __restrict__ src, const int* __restrict__ dst){
  int g = blockIdx.x*256 + threadIdx.x;
  int e = g >> 5;
  if (e >= EE) return;
  int lane = g & 31;
  int s = src[e], d = dst[e];
  float4 a = *(const float4*)(xt + (long)s*DD + lane*4);
  float4 b = *(const float4*)(xt + (long)d*DD + lane*4);
  float acc = b.x*lrelu(a.x) + b.y*lrelu(a.y) + b.z*lrelu(a.z) + b.w*lrelu(a.w);
  acc = wsum(acc);
  if (lane == 0){
    float di = g_dinv[s];
    float wv = acc / (1.f + expf(-di*acc));
    g_w[e] = wv;
    unsigned u = __float_as_uint(wv);
    u = (u & 0x80000000u) ? ~u : (u | 0x80000000u);
    atomicMax(&g_wmax[d], u);
  }
}
__global__ void k_exp(const int* __restrict__ dst){
  int e = blockIdx.x*256 + threadIdx.x;
  if (e >= EE) return;
  int d = dst[e];
  unsigned u = g_wmax[d];
  float wm = __uint_as_float((u & 0x80000000u) ? (u ^ 0x80000000u) : ~u);
  float ev = expf(g_w[e] - wm);
  g_ev[e] = ev;
  atomicAdd(&g_esum[d], ev);
}
__global__ void k_agg(const float* __restrict__ xt,
                      const int* __restrict__ src, const int* __restrict__ dst,
                      float* __restrict__ aggm){
  int g = blockIdx.x*256 + threadIdx.x;
  int e = g >> 5;
  if (e >= EE) return;
  int lane = g & 31;
  int s = src[e], d = dst[e];
  float att = g_ev[e] / (g_esum[d] + 1e-16f);
  float4 a = *(const float4*)(xt + (long)s*DD + lane*4);
  float* pa = aggm + (long)d*DD + lane*4;
  asm volatile("red.global.add.v4.f32 [%0], {%1, %2, %3, %4};"
               :: "l"(pa), "f"(att*a.x), "f"(att*a.y), "f"(att*a.z), "f"(att*a.w)
               : "memory");
}

// ---------------- tail ----------------
__global__ void k_mean(float* __restrict__ out_rep){
  int i = blockIdx.x*256 + threadIdx.x;
  if (i < MM*DX) g_kmod[i] = 0.f;
  if (i < NN*DX)
    out_rep[i] = 0.25f * (g_reps[i] + g_reps[(long)NN*DX + i]
                        + g_reps[2L*NN*DX + i] + g_reps[3L*NN*DX + i]);
}
__global__ void __launch_bounds__(64) k_kmod(const int* __restrict__ pi){
  int m = blockIdx.y, j = threadIdx.x;
  int b0 = blockIdx.x * 64;
  float acc = 0.f;
  #pragma unroll 4
  for (int t = 0; t < 64; t++){
    int p = pi[b0 + t];
    acc += g_reps[((long)m*NN + p)*DX + j];
  }
  atomicAdd(&g_kmod[m*DX + j], acc);
}
__global__ void k_kpvp(const float* __restrict__ kW, const float* __restrict__ vW){
  int tid = threadIdx.x;
  int m = tid >> 6, j = tid & 63;
  float s1 = 0.f, s2 = 0.f;
  #pragma unroll 8
  for (int k = 0; k < DX; k++){
    float km = g_kmod[m*DX + k] * (1.f/BB);
    s1 += km * kW[j*DX + k];
    s2 += km * vW[j*DX + k];
  }
  g_kp[m*DX + j] = s1;
  g_vp[m*DX + j] = s2;
}
__global__ void __launch_bounds__(64) k_final(
    const float* __restrict__ rep,
    const int* __restrict__ un, const int* __restrict__ pi, const int* __restrict__ ni,
    const float* __restrict__ qW,
    const float* __restrict__ mpW1, const float* __restrict__ mpb1,
    const float* __restrict__ mpW2, const float* __restrict__ mpb2,
    float* __restrict__ out_pos, float* __restrict__ out_neg, float* __restrict__ out_pred)
{
  int b = blockIdx.x, j = threadIdx.x;
  __shared__ float su[DX], sq[DX], sa[DX], sp[DX], sn[DX], sc[MM], red[DX];
  su[j] = rep[(long)un[b]*DX + j];
  sp[j] = rep[(long)pi[b]*DX + j];
  sn[j] = rep[(long)ni[b]*DX + j];
  __syncthreads();
  float q = 0.f;
  #pragma unroll 8
  for (int k = 0; k < DX; k++) q += su[k] * qW[j*DX + k];
  sq[j] = q;
  __syncthreads();
  if (j < MM){
    float s = 0.f;
    #pragma unroll 8
    for (int k = 0; k < DX; k++) s += sq[k] * g_kp[j*DX + k];
    sc[j] = s * 0.125f;
  }
  __syncthreads();
  float mx = fmaxf(fmaxf(sc[0], sc[1]), fmaxf(sc[2], sc[3]));
  float e0 = expf(sc[0]-mx), e1 = expf(sc[1]-mx), e2 = expf(sc[2]-mx), e3 = expf(sc[3]-mx);
  float es = e0 + e1 + e2 + e3;
  float av = (e0*g_vp[0*DX+j] + e1*g_vp[1*DX+j] + e2*g_vp[2*DX+j] + e3*g_vp[3*DX+j]) / es;
  sa[j] = av;
  red[j] = av * sp[j];
  __syncthreads();
  for (int s = 32; s > 0; s >>= 1){ if (j < s) red[j] += red[j+s]; __syncthreads(); }
  if (j == 0) out_pos[b] = red[0];
  __syncthreads();
  red[j] = av * sn[j];
  __syncthreads();
  for (int s = 32; s > 0; s >>= 1){ if (j < s) red[j] += red[j+s]; __syncthreads(); }
  if (j == 0) out_neg[b] = red[0];
  __syncthreads();
  float h = mpb1[j];
  #pragma unroll 8
  for (int k = 0; k < DX; k++) h += sa[k] * mpW1[j*2*DX + k];
  #pragma unroll 8
  for (int k = 0; k < DX; k++) h += sp[k] * mpW1[j*2*DX + DX + k];
  h = lrelu(h);
  red[j] = h * mpW2[j];
  __syncthreads();
  for (int s = 32; s > 0; s >>= 1){ if (j < s) red[j] += red[j+s]; __syncthreads(); }
  if (j == 0) out_pred[b] = red[0] + mpb2[0];
}

// ---------------- host ----------------
extern "C" void kernel_launch(void* const* d_in, const int* in_sizes, int n_in,
                              void* d_out, int out_size)
{
  const float* feats  = (const float*)d_in[0];
  const float* uf     = (const float*)d_in[1];
  const float* userW  = (const float*)d_in[2];
  const float* userb  = (const float*)d_in[3];
  const float* convW  = (const float*)d_in[4];
  const float* convb  = (const float*)d_in[5];
  const float* lin1W  = (const float*)d_in[6];
  const float* lin1b  = (const float*)d_in[7];
  const float* g1W    = (const float*)d_in[8];
  const float* g1b    = (const float*)d_in[9];
  const float* id_emb = (const float*)d_in[10];
  const float* qW     = (const float*)d_in[11];
  const float* kW     = (const float*)d_in[12];
  const float* vW     = (const float*)d_in[13];
  const float* mpW1   = (const float*)d_in[14];
  const float* mpb1   = (const float*)d_in[15];
  const float* mpW2   = (const float*)d_in[16];
  const float* mpb2   = (const float*)d_in[17];
  const int*   eidx   = (const int*)d_in[18];
  const int*   un     = (const int*)d_in[19];
  const int*   pi     = (const int*)d_in[20];
  const int*   ni     = (const int*)d_in[21];
  const int *src = eidx, *dst = eidx + EE;

  float* out      = (float*)d_out;
  float* out_pos  = out;
  float* out_neg  = out + BB;
  float* out_rep  = out + 2*BB;
  float* out_pred = out + 2*BB + (long)NN*DX;

  void* p;
  cudaGetSymbolAddress(&p, g_x);    float* x    = (float*)p;
  cudaGetSymbolAddress(&p, g_xt);   float* xt   = (float*)p;
  cudaGetSymbolAddress(&p, g_agg);  float* agg  = (float*)p;
  cudaGetSymbolAddress(&p, g_xh);   float* xh   = (float*)p;
  cudaGetSymbolAddress(&p, g_reps); float* reps = (float*)p;

  k_zero_agg<<<(MM*NN*DD/4 + 255)/256, 256>>>();
  k_zero_deg<<<(NN+255)/256, 256>>>();
  k_deg<<<(EE+255)/256, 256>>>(src);
  k_dinv<<<(NN+255)/256, 256>>>();

  k_norm_items<<<(MM*N_ITEM*32 + 255)/256, 256>>>(feats);
  {
    dim3 g(1, (N_USER+127)/128, MM);
    k_gemm<128,true,1><<<g, 256>>>(uf, userW, x + (long)N_ITEM*DD, N_USER, DD, DD,
                                   0, (long)DD*DD, (long)NN*DD, userb, DD, nullptr, 0);
  }
  k_norm_users<<<(MM*N_USER*32 + 255)/256, 256>>>();

  // xt = x @ convW
  {
    dim3 g(1, (NN+127)/128, MM);
    k_gemm<128,false,0><<<g, 256>>>(x, convW, xt, NN, DD, DD,
                                    (long)NN*DD, (long)DD*DD, (long)NN*DD,
                                    nullptr, 0, nullptr, 0);
  }
  // xh = lrelu(x @ lin1W^T + b) + id_emb
  {
    dim3 g(1, (NN+127)/128, MM);
    k_gemm<64,true,2><<<g, 256>>>(x, lin1W, xh, NN, DX, DD,
                                  (long)NN*DD, (long)DX*DD, (long)NN*DX,
                                  lin1b, DX, id_emb, 0);
  }

  // edge pipeline per modality (keeps 25.6MB xt hot in L2)
  for (int m = 0; m < MM; m++){
    const float* xtm = xt + (long)m*NN*DD;
    float* aggm = agg + (long)m*NN*DD;
    k_einit<<<(NN + 255)/256, 256>>>();
    k_ipwm<<<(EE*32 + 255)/256, 256>>>(xtm, src, dst);
    k_exp <<<(EE + 255)/256, 256>>>(dst);
    k_agg <<<(EE*32 + 255)/256, 256>>>(xtm, src, dst, aggm);
  }
  k_hnorm<<<(MM*NN*32 + 255)/256, 256>>>(convb);

  // reps = lrelu(h @ g1W^T + g1b + xh)
  {
    dim3 g(1, (NN+127)/128, MM);
    k_gemm<64,true,3><<<g, 256>>>(agg, g1W, reps, NN, DX, DD,
                                  (long)NN*DD, (long)DX*DD, (long)NN*DX,
                                  g1b, DX, xh, (long)NN*DX);
  }

  k_mean<<<(NN*DX + 255)/256, 256>>>(out_rep);
  k_kmod<<<dim3(BB/64, MM), 64>>>(pi);
  k_kpvp<<<1, 256>>>(kW, vW);
  k_final<<<BB, 64>>>(out_rep, un, pi, ni, qW, mpW1, mpb1, mpW2, mpb2,
                      out_pos, out_neg, out_pred);
}

// round 3
// speedup vs baseline: 1.1280x; 1.0470x over previous
#include <cuda_runtime.h>
#include <math.h>

#define MM 4
#define N_ITEM 40000
#define N_USER 10000
#define NN 50000
#define DD 128
#define DX 64
#define EE 400000
#define BB 4096

// ---------------- scratch (device globals; allocation-free) ----------------
__device__ float g_x   [MM*NN*DD];
__device__ float g_xt  [MM*NN*DD];
__device__ float g_agg [MM*NN*DD];   // h per modality
__device__ float g_xh  [MM*NN*DX];
__device__ float g_reps[MM*NN*DX];
__device__ float g_w   [EE];
__device__ float g_deg [NN];         // src-degree (float)
__device__ float g_dinv[NN];
__device__ int   g_degD[NN];         // dst-degree
__device__ int   g_off [NN+1];       // CSR offsets by dst
__device__ int   g_cur [NN];
__device__ int   g_eid [EE];         // edge ids sorted by dst
__device__ float g_kmod[MM*DX];
__device__ float g_kp  [MM*DX];
__device__ float g_vp  [MM*DX];

__device__ __forceinline__ float lrelu(float x){ return x > 0.f ? x : 0.01f*x; }
__device__ __forceinline__ float wsum(float v){
  #pragma unroll
  for (int o = 16; o; o >>= 1) v += __shfl_xor_sync(0xffffffffu, v, o);
  return v;
}
__device__ __forceinline__ float wmaxr(float v){
  #pragma unroll
  for (int o = 16; o; o >>= 1) v = fmaxf(v, __shfl_xor_sync(0xffffffffu, v, o));
  return v;
}

// ---------------- batched SGEMM: 128xBN tile, 8x(BN/16) per-thread ----------
// EPI 0: none | 1: tanh(+bias) | 2: lrelu(+bias)+add | 3: lrelu(+bias+add)
template<int BN, bool BT, int EPI>
__global__ void __launch_bounds__(256) k_gemm(
    const float* __restrict__ A, const float* __restrict__ B, float* __restrict__ C,
    int M, int N, int K, long sA, long sB, long sC,
    const float* __restrict__ bias, long sBias,
    const float* __restrict__ add, long sAdd)
{
  constexpr int BM = 128, BK = 16, TM = 8, TN = BN/16;
  __shared__ float As[BK][BM+4];
  __shared__ float Bs[BK][BN+4];
  int z = blockIdx.z;
  A += (long)z * sA;  B += (long)z * sB;  C += (long)z * sC;
  if (EPI)      bias += (long)z * sBias;
  if (EPI >= 2) add  += (long)z * sAdd;
  int m0 = blockIdx.y * BM, n0 = blockIdx.x * BN;
  int tid = threadIdx.x;
  int tx = tid & 15, ty = tid >> 4;
  float acc[TM][TN] = {};

  for (int k0 = 0; k0 < K; k0 += BK) {
    #pragma unroll
    for (int f = 0; f < 2; f++) {
      int idx = tid + f*256;
      int row = idx >> 2, kq = (idx & 3) << 2;
      float4 v = make_float4(0,0,0,0);
      if (m0 + row < M) v = *(const float4*)(A + (long)(m0+row)*K + k0 + kq);
      As[kq+0][row]=v.x; As[kq+1][row]=v.y; As[kq+2][row]=v.z; As[kq+3][row]=v.w;
    }
    if (BT) {
      constexpr int F = (BN*BK/4)/256;
      #pragma unroll
      for (int f = 0; f < F; f++) {
        int idx = tid + f*256;
        int row = idx >> 2, kq = (idx & 3) << 2;
        float4 v = *(const float4*)(B + (long)(n0+row)*K + k0 + kq);
        Bs[kq+0][row]=v.x; Bs[kq+1][row]=v.y; Bs[kq+2][row]=v.z; Bs[kq+3][row]=v.w;
      }
    } else {
      constexpr int F = (BK*BN/4)/256;
      #pragma unroll
      for (int f = 0; f < F; f++) {
        int idx = tid + f*256;
        int kk = idx / (BN/4), nq = (idx % (BN/4)) << 2;
        float4 v = *(const float4*)(B + (long)(k0+kk)*N + n0 + nq);
        *(float4*)&Bs[kk][nq] = v;
      }
    }
    __syncthreads();
    #pragma unroll
    for (int k = 0; k < BK; k++) {
      float a[TM], b[TN];
      *(float4*)&a[0] = *(const float4*)&As[k][ty<<2];
      *(float4*)&a[4] = *(const float4*)&As[k][64 + (ty<<2)];
      *(float4*)&b[0] = *(const float4*)&Bs[k][tx<<2];
      if constexpr (TN == 8)
        *(float4*)&b[4] = *(const float4*)&Bs[k][64 + (tx<<2)];
      #pragma unroll
      for (int i = 0; i < TM; i++)
        #pragma unroll
        for (int j = 0; j < TN; j++)
          acc[i][j] += a[i] * b[j];
    }
    __syncthreads();
  }
  #pragma unroll
  for (int i = 0; i < TM; i++) {
    int row = m0 + ((i < 4) ? (ty<<2)+i : 64 + (ty<<2) + (i-4));
    if (row >= M) continue;
    #pragma unroll
    for (int j = 0; j < TN; j++) {
      int col;
      if constexpr (TN == 8) col = n0 + ((j < 4) ? (tx<<2)+j : 64 + (tx<<2) + (j-4));
      else                   col = n0 + (tx<<2) + j;
      float v = acc[i][j];
      if (EPI == 1)      v = tanhf(v + bias[col]);
      else if (EPI == 2) v = lrelu(v + bias[col]) + add[(long)row*N + col];
      else if (EPI == 3) v = lrelu(v + bias[col] + add[(long)row*N + col]);
      C[(long)row*N + col] = v;
    }
  }
}

// ---------------- node-feature normalize (also zeroes degree counters) ------
__global__ void k_norm_items(const float* __restrict__ feats){
  int g = blockIdx.x*256 + threadIdx.x;
  if (g < NN){ g_deg[g] = 0.f; g_degD[g] = 0; }       // piggyback init
  int w = g >> 5, lane = g & 31;
  if (w >= MM*N_ITEM) return;
  int m = w / N_ITEM, i = w - m*N_ITEM;
  const float* in = feats + ((long)m*N_ITEM + i)*DD;
  float v[4], ss = 0.f;
  #pragma unroll
  for (int q = 0; q < 4; q++){ v[q] = in[q*32 + lane]; ss += v[q]*v[q]; }
  ss = wsum(ss);
  float rn = 1.f / fmaxf(sqrtf(ss), 1e-12f);
  float* o = g_x + ((long)m*NN + i)*DD;
  #pragma unroll
  for (int q = 0; q < 4; q++) o[q*32 + lane] = v[q]*rn;
}
__global__ void k_norm_users(){
  int g = blockIdx.x*256 + threadIdx.x;
  int w = g >> 5, lane = g & 31;
  if (w >= MM*N_USER) return;
  int m = w / N_USER, i = w - m*N_USER;
  float* p = g_x + ((long)m*NN + N_ITEM + i)*DD;
  float v[4], ss = 0.f;
  #pragma unroll
  for (int q = 0; q < 4; q++){ v[q] = p[q*32 + lane]; ss += v[q]*v[q]; }
  ss = wsum(ss);
  float rn = 1.f / fmaxf(sqrtf(ss), 1e-12f);
  #pragma unroll
  for (int q = 0; q < 4; q++) p[q*32 + lane] = v[q]*rn;
}

// ---------------- CSR build (once; graph is modality-invariant) -------------
__global__ void k_deg(const int* __restrict__ src, const int* __restrict__ dst){
  int e = blockIdx.x*256 + threadIdx.x;
  if (e < EE){ atomicAdd(&g_deg[src[e]], 1.f); atomicAdd(&g_degD[dst[e]], 1); }
}
__global__ void k_dinv(){
  int i = blockIdx.x*256 + threadIdx.x;
  if (i < NN){ float d = g_deg[i]; g_dinv[i] = d > 0.f ? 1.f/sqrtf(d) : 0.f; }
}
#define SCAN_T 1024
__global__ void __launch_bounds__(SCAN_T) k_scan(){
  __shared__ int ps[SCAN_T];
  int t = threadIdx.x;
  const int C = (NN + SCAN_T - 1)/SCAN_T;
  int lo = t*C, hi = lo+C < NN ? lo+C : NN;
  int s = 0;
  for (int i = lo; i < hi; i++) s += g_degD[i];
  ps[t] = s; __syncthreads();
  for (int off = 1; off < SCAN_T; off <<= 1){
    int v = (t >= off) ? ps[t-off] : 0;
    __syncthreads();
    ps[t] += v;
    __syncthreads();
  }
  int run = t ? ps[t-1] : 0;
  for (int i = lo; i < hi; i++){ int d = g_degD[i]; g_off[i] = run; g_cur[i] = run; run += d; }
  if (t == SCAN_T-1) g_off[NN] = run;
}
__global__ void k_scatter(const int* __restrict__ dst){
  int e = blockIdx.x*256 + threadIdx.x;
  if (e < EE){ int p = atomicAdd(&g_cur[dst[e]], 1); g_eid[p] = e; }
}

// ---------------- edge logits: w[e] = ip * sigmoid(dinv_src * ip) -----------
__global__ void k_ipwm(const float* __restrict__ xt,
                       const int* __restrict__ src, const int* __restrict__ dst){
  int g = blockIdx.x*256 + threadIdx.x;
  int e = g >> 5;
  if (e >= EE) return;
  int lane = g & 31;
  int s = src[e], d = dst[e];
  float4 a = *(const float4*)(xt + (long)s*DD + lane*4);
  float4 b = *(const float4*)(xt + (long)d*DD + lane*4);
  float acc = b.x*lrelu(a.x) + b.y*lrelu(a.y) + b.z*lrelu(a.z) + b.w*lrelu(a.w);
  acc = wsum(acc);
  if (lane == 0){
    float di = g_dinv[s];
    g_w[e] = acc / (1.f + expf(-di*acc));
  }
}

// --------- fused per-dst segment softmax + aggregate + bias + l2norm + lrelu
__global__ void __launch_bounds__(256) k_nodeagg(const float* __restrict__ xt,
                                                 const int* __restrict__ src,
                                                 const float* __restrict__ cb,
                                                 float* __restrict__ hout){
  int g = blockIdx.x*256 + threadIdx.x;
  int n = g >> 5, lane = g & 31;
  if (n >= NN) return;
  int o0 = g_off[n], o1 = g_off[n+1];
  // pass 1: segment max (lanes stride edges)
  float wm = -3.4e38f;
  for (int i = o0 + lane; i < o1; i += 32) wm = fmaxf(wm, g_w[g_eid[i]]);
  wm = wmaxr(wm);
  // pass 2: exp-sum
  float es = 0.f;
  for (int i = o0 + lane; i < o1; i += 32) es += expf(g_w[g_eid[i]] - wm);
  es = wsum(es);
  float rs = 1.f / (es + 1e-16f);
  // pass 3: weighted aggregate of src rows (warp covers 128 floats)
  float4 acc = make_float4(0,0,0,0);
  for (int i = o0; i < o1; i++){
    int e = g_eid[i];
    float att = expf(g_w[e] - wm) * rs;
    float4 a = *(const float4*)(xt + (long)src[e]*DD + lane*4);
    acc.x += att*a.x; acc.y += att*a.y; acc.z += att*a.z; acc.w += att*a.w;
  }
  // epilogue: + convb, l2norm, lrelu
  float4 b4 = *(const float4*)(cb + lane*4);
  acc.x += b4.x; acc.y += b4.y; acc.z += b4.z; acc.w += b4.w;
  float ss = acc.x*acc.x + acc.y*acc.y + acc.z*acc.z + acc.w*acc.w;
  ss = wsum(ss);
  float rn = 1.f / fmaxf(sqrtf(ss), 1e-12f);
  float4 o;
  o.x = lrelu(acc.x*rn); o.y = lrelu(acc.y*rn);
  o.z = lrelu(acc.z*rn); o.w = lrelu(acc.w*rn);
  *(float4*)(hout + (long)n*DD + lane*4) = o;
}

// ---------------- tail ----------------
__global__ void k_mean(float* __restrict__ out_rep){
  int i = blockIdx.x*256 + threadIdx.x;
  if (i < MM*DX) g_kmod[i] = 0.f;
  if (i < NN*DX)
    out_rep[i] = 0.25f * (g_reps[i] + g_reps[(long)NN*DX + i]
                        + g_reps[2L*NN*DX + i] + g_reps[3L*NN*DX + i]);
}
__global__ void __launch_bounds__(64) k_kmod(const int* __restrict__ pi){
  int m = blockIdx.y, j = threadIdx.x;
  int b0 = blockIdx.x * 64;
  float acc = 0.f;
  #pragma unroll 4
  for (int t = 0; t < 64; t++){
    int p = pi[b0 + t];
    acc += g_reps[((long)m*NN + p)*DX + j];
  }
  atomicAdd(&g_kmod[m*DX + j], acc);
}
__global__ void k_kpvp(const float* __restrict__ kW, const float* __restrict__ vW){
  int tid = threadIdx.x;
  int m = tid >> 6, j = tid & 63;
  float s1 = 0.f, s2 = 0.f;
  #pragma unroll 8
  for (int k = 0; k < DX; k++){
    float km = g_kmod[m*DX + k] * (1.f/BB);
    s1 += km * kW[j*DX + k];
    s2 += km * vW[j*DX + k];
  }
  g_kp[m*DX + j] = s1;
  g_vp[m*DX + j] = s2;
}
__global__ void __launch_bounds__(64) k_final(
    const float* __restrict__ rep,
    const int* __restrict__ un, const int* __restrict__ pi, const int* __restrict__ ni,
    const float* __restrict__ qW,
    const float* __restrict__ mpW1, const float* __restrict__ mpb1,
    const float* __restrict__ mpW2, const float* __restrict__ mpb2,
    float* __restrict__ out_pos, float* __restrict__ out_neg, float* __restrict__ out_pred)
{
  int b = blockIdx.x, j = threadIdx.x;
  __shared__ float su[DX], sq[DX], sa[DX], sp[DX], sn[DX], sc[MM], red[DX];
  su[j] = rep[(long)un[b]*DX + j];
  sp[j] = rep[(long)pi[b]*DX + j];
  sn[j] = rep[(long)ni[b]*DX + j];
  __syncthreads();
  float q = 0.f;
  #pragma unroll 8
  for (int k = 0; k < DX; k++) q += su[k] * qW[j*DX + k];
  sq[j] = q;
  __syncthreads();
  if (j < MM){
    float s = 0.f;
    #pragma unroll 8
    for (int k = 0; k < DX; k++) s += sq[k] * g_kp[j*DX + k];
    sc[j] = s * 0.125f;
  }
  __syncthreads();
  float mx = fmaxf(fmaxf(sc[0], sc[1]), fmaxf(sc[2], sc[3]));
  float e0 = expf(sc[0]-mx), e1 = expf(sc[1]-mx), e2 = expf(sc[2]-mx), e3 = expf(sc[3]-mx);
  float es = e0 + e1 + e2 + e3;
  float av = (e0*g_vp[0*DX+j] + e1*g_vp[1*DX+j] + e2*g_vp[2*DX+j] + e3*g_vp[3*DX+j]) / es;
  sa[j] = av;
  red[j] = av * sp[j];
  __syncthreads();
  for (int s = 32; s > 0; s >>= 1){ if (j < s) red[j] += red[j+s]; __syncthreads(); }
  if (j == 0) out_pos[b] = red[0];
  __syncthreads();
  red[j] = av * sn[j];
  __syncthreads();
  for (int s = 32; s > 0; s >>= 1){ if (j < s) red[j] += red[j+s]; __syncthreads(); }
  if (j == 0) out_neg[b] = red[0];
  __syncthreads();
  float h = mpb1[j];
  #pragma unroll 8
  for (int k = 0; k < DX; k++) h += sa[k] * mpW1[j*2*DX + k];
  #pragma unroll 8
  for (int k = 0; k < DX; k++) h += sp[k] * mpW1[j*2*DX + DX + k];
  h = lrelu(h);
  red[j] = h * mpW2[j];
  __syncthreads();
  for (int s = 32; s > 0; s >>= 1){ if (j < s) red[j] += red[j+s]; __syncthreads(); }
  if (j == 0) out_pred[b] = red[0] + mpb2[0];
}

// ---------------- host ----------------
extern "C" void kernel_launch(void* const* d_in, const int* in_sizes, int n_in,
                              void* d_out, int out_size)
{
  const float* feats  = (const float*)d_in[0];
  const float* uf     = (const float*)d_in[1];
  const float* userW  = (const float*)d_in[2];
  const float* userb  = (const float*)d_in[3];
  const float* convW  = (const float*)d_in[4];
  const float* convb  = (const float*)d_in[5];
  const float* lin1W  = (const float*)d_in[6];
  const float* lin1b  = (const float*)d_in[7];
  const float* g1W    = (const float*)d_in[8];
  const float* g1b    = (const float*)d_in[9];
  const float* id_emb = (const float*)d_in[10];
  const float* qW     = (const float*)d_in[11];
  const float* kW     = (const float*)d_in[12];
  const float* vW     = (const float*)d_in[13];
  const float* mpW1   = (const float*)d_in[14];
  const float* mpb1   = (const float*)d_in[15];
  const float* mpW2   = (const float*)d_in[16];
  const float* mpb2   = (const float*)d_in[17];
  const int*   eidx   = (const int*)d_in[18];
  const int*   un     = (const int*)d_in[19];
  const int*   pi     = (const int*)d_in[20];
  const int*   ni     = (const int*)d_in[21];
  const int *src = eidx, *dst = eidx + EE;

  float* out      = (float*)d_out;
  float* out_pos  = out;
  float* out_neg  = out + BB;
  float* out_rep  = out + 2*BB;
  float* out_pred = out + 2*BB + (long)NN*DX;

  void* p;
  cudaGetSymbolAddress(&p, g_x);    float* x    = (float*)p;
  cudaGetSymbolAddress(&p, g_xt);   float* xt   = (float*)p;
  cudaGetSymbolAddress(&p, g_agg);  float* agg  = (float*)p;
  cudaGetSymbolAddress(&p, g_xh);   float* xh   = (float*)p;
  cudaGetSymbolAddress(&p, g_reps); float* reps = (float*)p;

  // (1) items normalize (+ zero degree counters)
  k_norm_items<<<(MM*N_ITEM*32 + 255)/256, 256>>>(feats);
  // (2) user transform
  {
    dim3 g(1, (N_USER+127)/128, MM);
    k_gemm<128,true,1><<<g, 256>>>(uf, userW, x + (long)N_ITEM*DD, N_USER, DD, DD,
                                   0, (long)DD*DD, (long)NN*DD, userb, DD, nullptr, 0);
  }
  // (3) users normalize
  k_norm_users<<<(MM*N_USER*32 + 255)/256, 256>>>();
  // (4) xt = x @ convW   <-- ncu profile slot
  {
    dim3 g(1, (NN+127)/128, MM);
    k_gemm<128,false,0><<<g, 256>>>(x, convW, xt, NN, DD, DD,
                                    (long)NN*DD, (long)DD*DD, (long)NN*DD,
                                    nullptr, 0, nullptr, 0);
  }
  // (5) xh = lrelu(x @ lin1W^T + b) + id_emb
  {
    dim3 g(1, (NN+127)/128, MM);
    k_gemm<64,true,2><<<g, 256>>>(x, lin1W, xh, NN, DX, DD,
                                  (long)NN*DD, (long)DX*DD, (long)NN*DX,
                                  lin1b, DX, id_emb, 0);
  }
  // CSR build (once)
  k_deg    <<<(EE+255)/256, 256>>>(src, dst);
  k_dinv   <<<(NN+255)/256, 256>>>();
  k_scan   <<<1, SCAN_T>>>();
  k_scatter<<<(EE+255)/256, 256>>>(dst);

  // edge pipeline per modality (keeps 25.6MB xt slice hot in L2)
  for (int m = 0; m < MM; m++){
    const float* xtm = xt + (long)m*NN*DD;
    k_ipwm   <<<(EE*32 + 255)/256, 256>>>(xtm, src, dst);
    k_nodeagg<<<(NN*32 + 255)/256, 256>>>(xtm, src, convb + m*DD, agg + (long)m*NN*DD);
  }

  // reps = lrelu(h @ g1W^T + g1b + xh)
  {
    dim3 g(1, (NN+127)/128, MM);
    k_gemm<64,true,3><<<g, 256>>>(agg, g1W, reps, NN, DX, DD,
                                  (long)NN*DD, (long)DX*DD, (long)NN*DX,
                                  g1b, DX, xh, (long)NN*DX);
  }

  k_mean<<<(NN*DX + 255)/256, 256>>>(out_rep);
  k_kmod<<<dim3(BB/64, MM), 64>>>(pi);
  k_kpvp<<<1, 256>>>(kW, vW);
  k_final<<<BB, 64>>>(out_rep, un, pi, ni, qW, mpW1, mpb1, mpW2, mpb2,
                      out_pos, out_neg, out_pred);
}